// round 7
// baseline (speedup 1.0000x reference)
#include <cuda_runtime.h>
#include <math.h>
#include <float.h>

// R7 == R6 resubmission: R6 bench died in infra (container failed twice,
// same as R4; R5 with identical launch shape ran fine), so the fp32
// serial-ascending-k FMA hypothesis is still untested. Minimal-diff rerun.
//
// Hypothesis under test: reference matmul is plain fp32 FFMA with a serial
// per-output ascending-k accumulation chain; distances live on the
// ulp(||x||^2 ~ 128) grid via d = fl(fl(e2+x2) - 2*dot).

// Problem constants
#define NROWS 131072          // B*T = 64*2048
#define D     128
#define M     1024
#define DECAYF 0.999f
#define EPSF   1e-5f

// Output layout (tuple concat, all float32):
// quantized_st [16777216] | codes [131072] | loss [1] | perplexity [1]
// new_embedding [131072]  | new_ema_count [1024] | new_ema_weight [131072]
#define OFF_Q     0L
#define OFF_CODES 16777216L
#define OFF_LOSS  16908288L
#define OFF_PERP  16908289L
#define OFF_EMB   16908290L
#define OFF_CNT   17039362L
#define OFF_W     17040386L
#define OUT_TOTAL 17171458L

// Scratch (no allocations allowed -> device globals)
__device__ float g_e2[M];
__device__ float g_x2[NROWS];
__device__ float g_counts[M];
__device__ float g_dw[M * D];
__device__ float g_loss;

// ---------------------------------------------------------------------------
// Prep: zero scratch, compute ||e_m||^2 (order-insensitive: |e2| ~ 1e-4)
// ---------------------------------------------------------------------------
__global__ void k_prep(const float* __restrict__ emb) {
    int i = blockIdx.x * 256 + threadIdx.x;
    if (i < M * D) g_dw[i] = 0.0f;
    if (i < M) {
        g_counts[i] = 0.0f;
        const float* row = emb + i * D;
        float s = 0.0f;
#pragma unroll 8
        for (int d = 0; d < D; d++) {
            float v = row[d];
            s = __fadd_rn(s, __fmul_rn(v, v));
        }
        g_e2[i] = s;
    }
    if (i == 0) g_loss = 0.0f;
}

// ---------------------------------------------------------------------------
// ||x_r||^2 : only the BINADE of the result matters for the argmin (the
// combine's rounded offsets are independent of x2's low bits), so any
// reasonable fp32 reduction works. Block 128 threads = 2 rows x 64 lanes.
// ---------------------------------------------------------------------------
__global__ __launch_bounds__(128)
void k_x2(const float* __restrict__ x) {
    __shared__ float sw[2][2];
    const int rsub = threadIdx.x >> 6;            // row within block (0/1)
    const int t    = threadIdx.x & 63;            // virtual thread 0..63
    const long row = (long)blockIdx.x * 2 + rsub;
    float2 v = ((const float2*)(x + row * D))[t];
    float p = __fadd_rn(__fmul_rn(v.x, v.x), __fmul_rn(v.y, v.y));
#pragma unroll
    for (int off = 16; off > 0; off >>= 1)
        p = __fadd_rn(p, __shfl_down_sync(0xffffffffu, p, off));
    if ((t & 31) == 0) sw[rsub][t >> 5] = p;
    __syncthreads();
    if (t == 0) g_x2[row] = __fadd_rn(sw[rsub][0], sw[rsub][1]);
}

// ---------------------------------------------------------------------------
// Main kernel: tiled GEMM-argmin + gather + partial stats
// Dot: fp32 FMA, k strictly ascending (replicates cublas SIMT chain).
// Distance: d = fl( fl(e2 + x2) - fl(2*dot) ), first-index argmin.
// ---------------------------------------------------------------------------
#define XS 68        // x_t row stride (floats), %4==0 for LDS.128 alignment
#define ES 260       // e_t row stride (floats), %4==0
#define SM_FLOATS (128 * XS + 128 * ES + 64 + 16)
#define SM_BYTES  (SM_FLOATS * 4)

__global__ __launch_bounds__(256, 1)
void k_argmin(const float* __restrict__ x, const float* __restrict__ emb,
              float* __restrict__ out_q, float* __restrict__ out_codes,
              int write_aux) {
    extern __shared__ float sm[];
    float* xs = sm;                                   // [128][XS]
    float* es = sm + 128 * XS;                        // [128][ES]
    int*   sidx = (int*)(sm + 128 * XS + 128 * ES);   // [64]
    float* sred = (float*)(sidx + 64);                // [8+]

    const int tid = threadIdx.x;
    const int R0  = blockIdx.x * 64;                  // first row of this block
    const float4* x4 = (const float4*)x;              // row stride = 32 float4
    const float4* e4 = (const float4*)emb;

    // Load x tile [64 rows][128 d] transposed into xs[k][row]
#pragma unroll
    for (int i = 0; i < 8; i++) {
        int idx = tid + i * 256;          // 0..2047
        int r = idx >> 5, dv = idx & 31;
        float4 v = x4[(long)(R0 + r) * 32 + dv];
        int base = 4 * dv;
        xs[(base + 0) * XS + r] = v.x;
        xs[(base + 1) * XS + r] = v.y;
        xs[(base + 2) * XS + r] = v.z;
        xs[(base + 3) * XS + r] = v.w;
    }

    const int ty = tid >> 5;   // warp id -> row group (8 rows)
    const int tx = tid & 31;   // lane    -> code group (8 codes)

    // Per-row ||x||^2 (binade carrier for the grid combine)
    float x2r[8];
#pragma unroll
    for (int i = 0; i < 8; i++) x2r[i] = g_x2[R0 + ty * 8 + i];

    float mn[8]; int mi[8];
#pragma unroll
    for (int i = 0; i < 8; i++) { mn[i] = FLT_MAX; mi[i] = 0; }

    for (int ch = 0; ch < 4; ch++) {
        const int C0 = ch * 256;
        __syncthreads();   // previous chunk consumers done before overwrite
        // Load e chunk [256 codes][128 d] transposed into es[k][code]
#pragma unroll
        for (int i = 0; i < 32; i++) {
            int idx = tid + i * 256;      // 0..8191
            int c = idx >> 5, dv = idx & 31;
            float4 v = e4[(C0 + c) * 32 + dv];
            int base = 4 * dv;
            es[(base + 0) * ES + c] = v.x;
            es[(base + 1) * ES + c] = v.y;
            es[(base + 2) * ES + c] = v.z;
            es[(base + 3) * ES + c] = v.w;
        }
        __syncthreads();

        float acc[8][8];
#pragma unroll
        for (int i = 0; i < 8; i++)
#pragma unroll
            for (int j = 0; j < 8; j++) acc[i][j] = 0.0f;

        // k strictly ascending, serial fp32 FMA per accumulator (bit-exact
        // replica of the reference GEMM's per-output accumulation chain)
#pragma unroll 8
        for (int k = 0; k < 128; k++) {
            float4 xa = *(const float4*)&xs[k * XS + ty * 8];      // broadcast
            float4 xb = *(const float4*)&xs[k * XS + ty * 8 + 4];
            float4 ea = *(const float4*)&es[k * ES + tx * 8];      // conflict-free
            float4 eb = *(const float4*)&es[k * ES + tx * 8 + 4];
            float xv[8] = {xa.x, xa.y, xa.z, xa.w, xb.x, xb.y, xb.z, xb.w};
            float ev[8] = {ea.x, ea.y, ea.z, ea.w, eb.x, eb.y, eb.z, eb.w};
#pragma unroll
            for (int i = 0; i < 8; i++)
#pragma unroll
                for (int j = 0; j < 8; j++)
                    acc[i][j] = fmaf(xv[i], ev[j], acc[i][j]);
        }

        // d = fl( fl(e2 + x2) - fl(2*dot) ), exact reference rounding order.
        // 2*dot is exact (power-of-two scale). Ascending code order + strict <
        // keeps first index (argmin tie-break).
#pragma unroll
        for (int j = 0; j < 8; j++) {
            int c = C0 + tx * 8 + j;
            float e2v = g_e2[c];
#pragma unroll
            for (int i = 0; i < 8; i++) {
                float t = __fadd_rn(e2v, x2r[i]);
                float s = __fadd_rn(t, __fmul_rn(-2.0f, acc[i][j]));
                if (s < mn[i]) { mn[i] = s; mi[i] = c; }
            }
        }
    }

    // Cross-lane (per-row) lexicographic min reduction
#pragma unroll
    for (int off = 16; off > 0; off >>= 1) {
#pragma unroll
        for (int i = 0; i < 8; i++) {
            float om = __shfl_xor_sync(0xffffffffu, mn[i], off);
            int   oi = __shfl_xor_sync(0xffffffffu, mi[i], off);
            if (om < mn[i] || (om == mn[i] && oi < mi[i])) { mn[i] = om; mi[i] = oi; }
        }
    }
    if (tx == 0) {
#pragma unroll
        for (int i = 0; i < 8; i++) sidx[ty * 8 + i] = mi[i];
    }
    __syncthreads();

    // Finalize: 4 threads per row. Gather code row, write quantized_st with
    // reference rounding x + (q - x), accumulate loss & dw & counts.
    const int r   = tid >> 2;
    const int sub = tid & 3;
    const int code = sidx[r];
    const long gr = (long)R0 + r;
    const float4* eRow = e4 + code * 32;
    const float4* xRow = x4 + gr * 32;
    float4* qRow = (float4*)out_q + gr * 32;
    float lsum = 0.0f;
#pragma unroll
    for (int v = 0; v < 8; v++) {
        int dv = sub * 8 + v;
        float4 xv = xRow[dv];
        float4 qv = eRow[dv];
        float4 o;
        o.x = __fadd_rn(xv.x, __fsub_rn(qv.x, xv.x));
        o.y = __fadd_rn(xv.y, __fsub_rn(qv.y, xv.y));
        o.z = __fadd_rn(xv.z, __fsub_rn(qv.z, xv.z));
        o.w = __fadd_rn(xv.w, __fsub_rn(qv.w, xv.w));
        qRow[dv] = o;
        float dx = xv.x - qv.x, dy = xv.y - qv.y, dz = xv.z - qv.z, dw_ = xv.w - qv.w;
        lsum += dx * dx + dy * dy + dz * dz + dw_ * dw_;
        float* dwp = &g_dw[code * 128 + dv * 4];
        atomicAdd(dwp + 0, xv.x);
        atomicAdd(dwp + 1, xv.y);
        atomicAdd(dwp + 2, xv.z);
        atomicAdd(dwp + 3, xv.w);
    }
    if (sub == 0) {
        atomicAdd(&g_counts[code], 1.0f);
        if (write_aux) out_codes[gr] = (float)code;
    }

    // Block-reduce loss partial, single atomic per block
#pragma unroll
    for (int off = 16; off > 0; off >>= 1)
        lsum += __shfl_xor_sync(0xffffffffu, lsum, off);
    if (tx == 0) sred[ty] = lsum;
    __syncthreads();
    if (tid == 0) {
        float s = 0.0f;
#pragma unroll
        for (int i = 0; i < 8; i++) s += sred[i];
        atomicAdd(&g_loss, s);
    }
}

// ---------------------------------------------------------------------------
// EMA scalar part: normalized counts, loss, perplexity
// ---------------------------------------------------------------------------
__global__ void k_ema1(const float* __restrict__ ema_count,
                       float* __restrict__ out_count,
                       float* __restrict__ out_loss,
                       float* __restrict__ out_perp) {
    __shared__ float sred[1024];
    int m = threadIdx.x;
    float cnt = g_counts[m];
    float raw = DECAYF * ema_count[m] + (1.0f - DECAYF) * cnt;
    sred[m] = raw;
    __syncthreads();
    for (int s = 512; s > 0; s >>= 1) {
        if (m < s) sred[m] += sred[m + s];
        __syncthreads();
    }
    float n = sred[0];
    __syncthreads();
    float newc = (raw + EPSF) / (n + 1024.0f * EPSF) * n;
    out_count[m] = newc;

    float p = cnt * (1.0f / 131072.0f);
    sred[m] = -p * logf(p + 1e-10f);
    __syncthreads();
    for (int s = 512; s > 0; s >>= 1) {
        if (m < s) sred[m] += sred[m + s];
        __syncthreads();
    }
    if (m == 0) {
        *out_perp = expf(sred[0]);
        *out_loss = 0.25f * g_loss * (1.0f / 16777216.0f);
    }
}

// ---------------------------------------------------------------------------
// EMA vector part: new_ema_weight, new_embedding
// ---------------------------------------------------------------------------
__global__ void k_ema2(const float* __restrict__ ema_weight,
                       const float* __restrict__ newc,   // from d_out (k_ema1)
                       float* __restrict__ out_w,
                       float* __restrict__ out_emb) {
    int i = blockIdx.x * 256 + threadIdx.x;   // < 131072
    float w = DECAYF * ema_weight[i] + (1.0f - DECAYF) * g_dw[i];
    out_w[i] = w;
    out_emb[i] = w / newc[i >> 7];
}

// ---------------------------------------------------------------------------
extern "C" void kernel_launch(void* const* d_in, const int* in_sizes, int n_in,
                              void* d_out, int out_size) {
    const float* x          = (const float*)d_in[0];
    const float* emb        = (const float*)d_in[1];
    const float* ema_count  = (const float*)d_in[2];
    const float* ema_weight = (const float*)d_in[3];
    float* out = (float*)d_out;

    const int full = (out_size >= (int)OUT_TOTAL) ? 1 : 0;

    cudaFuncSetAttribute(k_argmin, cudaFuncAttributeMaxDynamicSharedMemorySize,
                         SM_BYTES);

    k_prep<<<512, 256>>>(emb);
    k_x2<<<NROWS / 2, 128>>>(x);
    k_argmin<<<NROWS / 64, 256, SM_BYTES>>>(
        x, emb, out + OFF_Q, full ? (out + OFF_CODES) : (out + OFF_Q), full);
    if (full) {
        k_ema1<<<1, 1024>>>(ema_count, out + OFF_CNT, out + OFF_LOSS,
                            out + OFF_PERP);
        k_ema2<<<512, 256>>>(ema_weight, out + OFF_CNT, out + OFF_W,
                             out + OFF_EMB);
    }
}

// round 11
// speedup vs baseline: 1.4016x; 1.4016x over previous
#include <cuda_runtime.h>
#include <cuda_bf16.h>
#include <cuda_pipeline.h>
#include <math.h>
#include <float.h>

// R11 == R9 resubmission (3rd attempt): R9/R10 benches died in the broker
// ("container failed twice") — the same wrapper error that hit R4 and R6,
// whose identical-byte resubmissions then ran fine. Kernel audited: no
// divergent barriers, no OOB, no hang path; an in-kernel fault would report
// "Kernel execution failed", not a container failure.
//
// Two-pass VQ argmin, pass A on mma.sync (base-target HMMA; tcgen05 is
// unavailable: harness compiles PTX at compute_100, not compute_100a).
//  Pass A (k_approx): bf16 m16n8k16 mma.sync scores -> per-row running min +
//    lazy candidate list, margin 6e-4 (>= 2x worst-case bf16 rounding error).
//  Pass B (k_exact): bit-exact R7 scoring over candidates + R7 epilogue.
// Invariant protected: final code decision bit-identical to R7.

#define NROWS 131072
#define D     128
#define M     1024
#define DECAYF 0.999f
#define EPSF   1e-5f

#define OFF_Q     0L
#define OFF_CODES 16777216L
#define OFF_LOSS  16908288L
#define OFF_PERP  16908289L
#define OFF_EMB   16908290L
#define OFF_CNT   17039362L
#define OFF_W     17040386L
#define OUT_TOTAL 17171458L

#define CHUNKS   8
#define CN       128
#define CAND_MAX 24
#define MARGIN   6e-4f

// Scratch
__device__ float g_e2[M];
__device__ float g_x2[NROWS];
__device__ float g_counts[M];
__device__ float g_dw[M * D];
__device__ float g_loss;
__device__ __nv_bfloat16 g_ebf[M * D];      // bf16 image of embedding
__device__ int            g_ccnt[NROWS];
__device__ unsigned short g_cand[(long)NROWS * CAND_MAX];

__device__ __forceinline__ unsigned smem_u32(const void* p) {
    unsigned a;
    asm("{ .reg .u64 t; cvta.to.shared.u64 t, %1; cvt.u32.u64 %0, t; }"
        : "=r"(a) : "l"(p));
    return a;
}

// ---------------------------------------------------------------------------
// Prep: zero scratch, exact ||e||^2, bf16 embedding image
// ---------------------------------------------------------------------------
__global__ void k_prep(const float* __restrict__ emb) {
    int i = blockIdx.x * 256 + threadIdx.x;       // 0..131071
    if (i < M * D) {
        g_dw[i] = 0.0f;
        g_ebf[i] = __float2bfloat16_rn(emb[i]);
    }
    if (i < M) {
        g_counts[i] = 0.0f;
        const float* row = emb + i * D;
        float s = 0.0f;
#pragma unroll 8
        for (int d = 0; d < D; d++) { float v = row[d]; s = __fadd_rn(s, __fmul_rn(v, v)); }
        g_e2[i] = s;
    }
    if (i == 0) g_loss = 0.0f;
}

// ---------------------------------------------------------------------------
// ||x||^2 (binade carrier; validated R7)
// ---------------------------------------------------------------------------
__global__ __launch_bounds__(128)
void k_x2(const float* __restrict__ x) {
    __shared__ float sw[2][2];
    const int rsub = threadIdx.x >> 6;
    const int t    = threadIdx.x & 63;
    const long row = (long)blockIdx.x * 2 + rsub;
    float2 v = ((const float2*)(x + row * D))[t];
    float p = __fadd_rn(__fmul_rn(v.x, v.x), __fmul_rn(v.y, v.y));
#pragma unroll
    for (int off = 16; off > 0; off >>= 1)
        p = __fadd_rn(p, __shfl_down_sync(0xffffffffu, p, off));
    if ((t & 31) == 0) sw[rsub][t >> 5] = p;
    __syncthreads();
    if (t == 0) g_x2[row] = __fadd_rn(sw[rsub][0], sw[rsub][1]);
}

// ---------------------------------------------------------------------------
// Pass A: mma.sync bf16 approx scores + candidate lists.
// CTA 256 thr / 128 rows. Warp tile 32 rows x 64 codes; chunk = 128 codes.
// smem: xs bf16 [128][136] | eb bf16 [2][128][136] | scores f32 [128][130]
//       | e2s f32 [1024]
// ---------------------------------------------------------------------------
#define XES 136                         // halves per row (272 B)
#define SCS 130                         // floats per scores row
#define SM_XS_B     (128 * XES * 2)     // 34816
#define SM_EB_B     (128 * XES * 2)     // per buffer
#define SM_SC_OFF   (SM_XS_B + 2 * SM_EB_B)          // 104448
#define SM_E2_OFF   (SM_SC_OFF + 128 * SCS * 4)      // 171008
#define SMEMA_BYTES (SM_E2_OFF + 4096)               // 175104

#define LDMX4(r0, r1, r2, r3, a) \
    asm volatile("ldmatrix.sync.aligned.m8n8.x4.shared.b16 {%0,%1,%2,%3}, [%4];" \
        : "=r"(r0), "=r"(r1), "=r"(r2), "=r"(r3) : "r"(a))

#define MMA16816(c, a, b) \
    asm volatile("mma.sync.aligned.m16n8k16.row.col.f32.bf16.bf16.f32 " \
        "{%0,%1,%2,%3}, {%4,%5,%6,%7}, {%8,%9}, {%0,%1,%2,%3};" \
        : "+f"((c)[0]), "+f"((c)[1]), "+f"((c)[2]), "+f"((c)[3]) \
        : "r"((a)[0]), "r"((a)[1]), "r"((a)[2]), "r"((a)[3]), \
          "r"((b)[0]), "r"((b)[1]))

__global__ __launch_bounds__(256, 1)
void k_approx(const float* __restrict__ x) {
    extern __shared__ unsigned char sm[];
    __nv_bfloat16* xs = (__nv_bfloat16*)sm;
    __nv_bfloat16* eb0 = (__nv_bfloat16*)(sm + SM_XS_B);
    float* scores = (float*)(sm + SM_SC_OFF);
    float* e2s    = (float*)(sm + SM_E2_OFF);
    const unsigned xs_a  = smem_u32(xs);
    const unsigned eb_a  = smem_u32(eb0);

    const int tid = threadIdx.x, w = tid >> 5, lane = tid & 31;
    const int R0 = blockIdx.x * 128;

    // e2 -> smem
    for (int i = tid; i < 1024; i += 256) e2s[i] = g_e2[i];

    // prefetch e chunk 0
    {
        const unsigned char* src = (const unsigned char*)g_ebf;
        unsigned char* dst = (unsigned char*)eb0;
        for (int i = tid; i < 2048; i += 256) {
            int r = i >> 4, o = (i & 15) * 16;
            __pipeline_memcpy_async(dst + r * 272 + o, src + r * 256 + o, 16);
        }
        __pipeline_commit();
    }

    // x tile -> bf16 smem [row][k], padded stride
    {
        const float4* x4 = (const float4*)x;
        for (int i = tid; i < 4096; i += 256) {
            int r = i >> 5, kg = i & 31;
            float4 v = x4[(long)(R0 + r) * 32 + kg];
            __nv_bfloat162 p0 = __floats2bfloat162_rn(v.x, v.y);
            __nv_bfloat162 p1 = __floats2bfloat162_rn(v.z, v.w);
            *(uint2*)&xs[r * XES + kg * 4] =
                make_uint2(*(unsigned*)&p0, *(unsigned*)&p1);
        }
    }

    const int rg = w >> 1;                 // row group: rows rg*32..+31
    const int cg = w & 1;                  // code half: cg*64..+63
    const int rbase = rg * 32;

    float runmin = FLT_MAX;
    int cnt = 0;
    unsigned short* crow = g_cand + ((long)R0 + tid) * CAND_MAX;

    for (int ch = 0; ch < CHUNKS; ch++) {
        __pipeline_wait_prior(0);
        __syncthreads();
        const unsigned ebc = eb_a + (unsigned)((ch & 1) * SM_EB_B);

        // prefetch next chunk
        if (ch + 1 < CHUNKS) {
            const unsigned char* src =
                (const unsigned char*)g_ebf + (ch + 1) * CN * 256;
            unsigned char* dst = (unsigned char*)eb0 + ((ch + 1) & 1) * SM_EB_B;
            for (int i = tid; i < 2048; i += 256) {
                int r = i >> 4, o = (i & 15) * 16;
                __pipeline_memcpy_async(dst + r * 272 + o, src + r * 256 + o, 16);
            }
        }
        __pipeline_commit();

        float acc[2][8][4];
#pragma unroll
        for (int mt = 0; mt < 2; mt++)
#pragma unroll
            for (int nt = 0; nt < 8; nt++)
#pragma unroll
                for (int q = 0; q < 4; q++) acc[mt][nt][q] = 0.0f;

#pragma unroll
        for (int ks = 0; ks < 8; ks++) {
            unsigned a[2][4];
#pragma unroll
            for (int mt = 0; mt < 2; mt++) {
                int row = rbase + mt * 16 + (lane & 7) + ((lane >> 3) & 1) * 8;
                int ko  = ks * 16 + (lane >> 4) * 8;
                unsigned ad = xs_a + (unsigned)(row * XES + ko) * 2;
                LDMX4(a[mt][0], a[mt][1], a[mt][2], a[mt][3], ad);
            }
            unsigned b[8][2];
#pragma unroll
            for (int p = 0; p < 4; p++) {
                int g = lane >> 3, ri = lane & 7;
                int code = cg * 64 + p * 16 + (g >> 1) * 8 + ri;
                int ko   = ks * 16 + (g & 1) * 8;
                unsigned ad = ebc + (unsigned)(code * XES + ko) * 2;
                LDMX4(b[2 * p][0], b[2 * p][1], b[2 * p + 1][0], b[2 * p + 1][1], ad);
            }
#pragma unroll
            for (int mt = 0; mt < 2; mt++)
#pragma unroll
                for (int nt = 0; nt < 8; nt++)
                    MMA16816(acc[mt][nt], a[mt], b[nt]);
        }

        // scores[row][col] = e2 - 2*dot  (approx; margin covers all error)
#pragma unroll
        for (int mt = 0; mt < 2; mt++)
#pragma unroll
            for (int nt = 0; nt < 8; nt++) {
                int row = rbase + mt * 16 + (lane >> 2);
                int col = cg * 64 + nt * 8 + (lane & 3) * 2;
                float e2a = e2s[ch * CN + col], e2b = e2s[ch * CN + col + 1];
                float2 s01 = make_float2(fmaf(-2.0f, acc[mt][nt][0], e2a),
                                         fmaf(-2.0f, acc[mt][nt][1], e2b));
                float2 s23 = make_float2(fmaf(-2.0f, acc[mt][nt][2], e2a),
                                         fmaf(-2.0f, acc[mt][nt][3], e2b));
                *(float2*)&scores[row * SCS + col] = s01;
                *(float2*)&scores[(row + 8) * SCS + col] = s23;
            }
        __syncthreads();

        // per-row scan (thread tid < 128 owns row tid)
        if (tid < 128) {
            const float* sr = &scores[tid * SCS];
            float rm = runmin;
#pragma unroll 4
            for (int c = 0; c < CN; c++) {
                float s = sr[c];
                if (s < rm + MARGIN) {
                    if (cnt < CAND_MAX) crow[cnt] = (unsigned short)(ch * CN + c);
                    cnt++;
                    if (s < rm) rm = s;
                }
            }
            runmin = rm;
        }
        __syncthreads();
    }
    if (tid < 128) g_ccnt[R0 + tid] = cnt;   // >CAND_MAX => pass B full-scan
}

// ---------------------------------------------------------------------------
// Pass B: exact rescoring (bit-exact R7 math) + full epilogue.
// CTA 128 thr, 32 rows, 4 threads/row.
// ---------------------------------------------------------------------------
#define BXS 132
__global__ __launch_bounds__(128, 1)
void k_exact(const float* __restrict__ x, const float* __restrict__ emb,
             float* __restrict__ out_q, float* __restrict__ out_codes,
             int write_aux) {
    __shared__ float xs[32 * BXS];
    const int tid = threadIdx.x;
    const int R0 = blockIdx.x * 32;
    const float4* x4 = (const float4*)x;

    for (int i = tid; i < 32 * 32; i += 128) {
        int r = i >> 5, dv = i & 31;
        *(float4*)&xs[r * BXS + dv * 4] = x4[(long)(R0 + r) * 32 + dv];
    }
    __syncthreads();

    const int r = tid >> 2, sub = tid & 3;
    const long gr = (long)R0 + r;
    const float x2v = g_x2[gr];
    const int cnt = g_ccnt[gr];
    const unsigned short* crow = g_cand + gr * CAND_MAX;

    float best = FLT_MAX;
    int bi = 0x7fffffff;
    if (cnt <= CAND_MAX) {
        for (int j = sub; j < cnt; j += 4) {
            int code = crow[j];
            const float* er = emb + code * 128;
            float acc = 0.0f;
#pragma unroll 16
            for (int k = 0; k < 128; k++) acc = fmaf(xs[r * BXS + k], er[k], acc);
            float t = __fadd_rn(g_e2[code], x2v);
            float s = __fadd_rn(t, __fmul_rn(-2.0f, acc));
            if (s < best || (s == best && code < bi)) { best = s; bi = code; }
        }
    } else {  // overflow: exact scan of all codes
        for (int code = sub; code < 1024; code += 4) {
            const float* er = emb + code * 128;
            float acc = 0.0f;
#pragma unroll 16
            for (int k = 0; k < 128; k++) acc = fmaf(xs[r * BXS + k], er[k], acc);
            float t = __fadd_rn(g_e2[code], x2v);
            float s = __fadd_rn(t, __fmul_rn(-2.0f, acc));
            if (s < best || (s == best && code < bi)) { best = s; bi = code; }
        }
    }
#pragma unroll
    for (int o = 1; o < 4; o <<= 1) {
        float ob = __shfl_xor_sync(0xffffffffu, best, o);
        int   oi = __shfl_xor_sync(0xffffffffu, bi, o);
        if (ob < best || (ob == best && oi < bi)) { best = ob; bi = oi; }
    }
    const int code = bi;

    // R7 epilogue (verbatim math)
    const float4* eRow = (const float4*)emb + code * 32;
    float4* qRow = (float4*)out_q + gr * 32;
    float lsum = 0.0f;
#pragma unroll
    for (int v = 0; v < 8; v++) {
        int dv = sub * 8 + v;
        float4 xv = *(float4*)&xs[r * BXS + dv * 4];
        float4 qv = eRow[dv];
        float4 o;
        o.x = __fadd_rn(xv.x, __fsub_rn(qv.x, xv.x));
        o.y = __fadd_rn(xv.y, __fsub_rn(qv.y, xv.y));
        o.z = __fadd_rn(xv.z, __fsub_rn(qv.z, xv.z));
        o.w = __fadd_rn(xv.w, __fsub_rn(qv.w, xv.w));
        qRow[dv] = o;
        float dx = xv.x - qv.x, dy = xv.y - qv.y, dz = xv.z - qv.z, dw_ = xv.w - qv.w;
        lsum += dx * dx + dy * dy + dz * dz + dw_ * dw_;
        float* dwp = &g_dw[code * 128 + dv * 4];
        atomicAdd(dwp + 0, xv.x);
        atomicAdd(dwp + 1, xv.y);
        atomicAdd(dwp + 2, xv.z);
        atomicAdd(dwp + 3, xv.w);
    }
    if (sub == 0) {
        atomicAdd(&g_counts[code], 1.0f);
        if (write_aux) out_codes[gr] = (float)code;
    }
#pragma unroll
    for (int o = 16; o > 0; o >>= 1)
        lsum += __shfl_xor_sync(0xffffffffu, lsum, o);
    if ((tid & 31) == 0) atomicAdd(&g_loss, lsum);
}

// ---------------------------------------------------------------------------
// EMA scalar part (validated R7)
// ---------------------------------------------------------------------------
__global__ void k_ema1(const float* __restrict__ ema_count,
                       float* __restrict__ out_count,
                       float* __restrict__ out_loss,
                       float* __restrict__ out_perp) {
    __shared__ float sred[1024];
    int m = threadIdx.x;
    float cnt = g_counts[m];
    float raw = DECAYF * ema_count[m] + (1.0f - DECAYF) * cnt;
    sred[m] = raw;
    __syncthreads();
    for (int s = 512; s > 0; s >>= 1) {
        if (m < s) sred[m] += sred[m + s];
        __syncthreads();
    }
    float n = sred[0];
    __syncthreads();
    float newc = (raw + EPSF) / (n + 1024.0f * EPSF) * n;
    out_count[m] = newc;

    float p = cnt * (1.0f / 131072.0f);
    sred[m] = -p * logf(p + 1e-10f);
    __syncthreads();
    for (int s = 512; s > 0; s >>= 1) {
        if (m < s) sred[m] += sred[m + s];
        __syncthreads();
    }
    if (m == 0) {
        *out_perp = expf(sred[0]);
        *out_loss = 0.25f * g_loss * (1.0f / 16777216.0f);
    }
}

// ---------------------------------------------------------------------------
// EMA vector part (validated R7)
// ---------------------------------------------------------------------------
__global__ void k_ema2(const float* __restrict__ ema_weight,
                       const float* __restrict__ newc,
                       float* __restrict__ out_w,
                       float* __restrict__ out_emb) {
    int i = blockIdx.x * 256 + threadIdx.x;
    float w = DECAYF * ema_weight[i] + (1.0f - DECAYF) * g_dw[i];
    out_w[i] = w;
    out_emb[i] = w / newc[i >> 7];
}

// ---------------------------------------------------------------------------
extern "C" void kernel_launch(void* const* d_in, const int* in_sizes, int n_in,
                              void* d_out, int out_size) {
    const float* x          = (const float*)d_in[0];
    const float* emb        = (const float*)d_in[1];
    const float* ema_count  = (const float*)d_in[2];
    const float* ema_weight = (const float*)d_in[3];
    float* out = (float*)d_out;

    const int full = (out_size >= (int)OUT_TOTAL) ? 1 : 0;

    cudaFuncSetAttribute(k_approx, cudaFuncAttributeMaxDynamicSharedMemorySize,
                         SMEMA_BYTES);

    k_prep<<<512, 256>>>(emb);
    k_x2<<<NROWS / 2, 128>>>(x);
    k_approx<<<NROWS / 128, 256, SMEMA_BYTES>>>(x);
    k_exact<<<NROWS / 32, 128>>>(x, emb, out + OFF_Q,
                                 full ? (out + OFF_CODES) : (out + OFF_Q), full);
    if (full) {
        k_ema1<<<1, 1024>>>(ema_count, out + OFF_CNT, out + OFF_LOSS,
                            out + OFF_PERP);
        k_ema2<<<512, 256>>>(ema_weight, out + OFF_CNT, out + OFF_W,
                             out + OFF_EMB);
    }
}

// round 12
// speedup vs baseline: 2.1875x; 1.5607x over previous
#include <cuda_runtime.h>
#include <cuda_bf16.h>
#include <cuda_pipeline.h>
#include <math.h>
#include <float.h>

// R12: two-pass VQ argmin (pass A mma.sync HMMA, pass B exact rescore).
// vs R11: pass B split into warp-per-row k_rescore (lane-per-candidate,
// float4 vectorized, exact serial-k chains) + k_final (coalesced epilogue);
// k_approx shrunk to 107KB smem (single e-buffer + bf16 scores) -> 2 CTA/SM.
// Invariant: final code decision bit-identical to R7 (exact rescoring of a
// margin-guaranteed candidate superset, first-index tie-break).

#define NROWS 131072
#define D     128
#define M     1024
#define DECAYF 0.999f
#define EPSF   1e-5f

#define OFF_Q     0L
#define OFF_CODES 16777216L
#define OFF_LOSS  16908288L
#define OFF_PERP  16908289L
#define OFF_EMB   16908290L
#define OFF_CNT   17039362L
#define OFF_W     17040386L
#define OUT_TOTAL 17171458L

#define CHUNKS   8
#define CN       128
#define CAND_MAX 32
#define MARGIN   2e-3f

// Scratch
__device__ float g_e2[M];
__device__ float g_x2[NROWS];
__device__ float g_counts[M];
__device__ float g_dw[M * D];
__device__ float g_loss;
__device__ __nv_bfloat16 g_ebf[M * D];
__device__ int            g_ccnt[NROWS];
__device__ unsigned short g_cand[(long)NROWS * CAND_MAX];
__device__ float          g_cs[(long)NROWS * CAND_MAX];

__device__ __forceinline__ unsigned smem_u32(const void* p) {
    unsigned a;
    asm("{ .reg .u64 t; cvta.to.shared.u64 t, %1; cvt.u32.u64 %0, t; }"
        : "=r"(a) : "l"(p));
    return a;
}

// ---------------------------------------------------------------------------
// Prep: zero scratch, exact ||e||^2, bf16 embedding image
// ---------------------------------------------------------------------------
__global__ void k_prep(const float* __restrict__ emb) {
    int i = blockIdx.x * 256 + threadIdx.x;
    if (i < M * D) {
        g_dw[i] = 0.0f;
        g_ebf[i] = __float2bfloat16_rn(emb[i]);
    }
    if (i < M) {
        g_counts[i] = 0.0f;
        const float* row = emb + i * D;
        float s = 0.0f;
#pragma unroll 8
        for (int d = 0; d < D; d++) { float v = row[d]; s = __fadd_rn(s, __fmul_rn(v, v)); }
        g_e2[i] = s;
    }
    if (i == 0) g_loss = 0.0f;
}

// ---------------------------------------------------------------------------
// ||x||^2 (binade carrier; validated R7)
// ---------------------------------------------------------------------------
__global__ __launch_bounds__(128)
void k_x2(const float* __restrict__ x) {
    __shared__ float sw[2][2];
    const int rsub = threadIdx.x >> 6;
    const int t    = threadIdx.x & 63;
    const long row = (long)blockIdx.x * 2 + rsub;
    float2 v = ((const float2*)(x + row * D))[t];
    float p = __fadd_rn(__fmul_rn(v.x, v.x), __fmul_rn(v.y, v.y));
#pragma unroll
    for (int off = 16; off > 0; off >>= 1)
        p = __fadd_rn(p, __shfl_down_sync(0xffffffffu, p, off));
    if ((t & 31) == 0) sw[rsub][t >> 5] = p;
    __syncthreads();
    if (t == 0) g_x2[row] = __fadd_rn(sw[rsub][0], sw[rsub][1]);
}

// ---------------------------------------------------------------------------
// Pass A: mma.sync bf16 approx scores + candidate lists.
// CTA 256 thr / 128 rows. Single e-buffer, bf16 scores -> 107KB smem,
// 2 CTAs/SM. Copy of chunk ch+1 overlaps the scan of chunk ch.
// ---------------------------------------------------------------------------
#define XES 136                          // bf16 per row (272 B)
#define SCS 130                          // bf16 per scores row (260 B)
#define SM_XS_B   (128 * XES * 2)        // 34816
#define SM_EB_OFF SM_XS_B
#define SM_EB_B   (128 * XES * 2)        // 34816
#define SM_SC_OFF (SM_EB_OFF + SM_EB_B)  // 69632
#define SM_SC_B   (128 * SCS * 2)        // 33280
#define SM_E2_OFF (SM_SC_OFF + SM_SC_B)  // 102912
#define SMEMA_BYTES (SM_E2_OFF + 4096)   // 107008

#define LDMX4(r0, r1, r2, r3, a) \
    asm volatile("ldmatrix.sync.aligned.m8n8.x4.shared.b16 {%0,%1,%2,%3}, [%4];" \
        : "=r"(r0), "=r"(r1), "=r"(r2), "=r"(r3) : "r"(a))

#define MMA16816(c, a, b) \
    asm volatile("mma.sync.aligned.m16n8k16.row.col.f32.bf16.bf16.f32 " \
        "{%0,%1,%2,%3}, {%4,%5,%6,%7}, {%8,%9}, {%0,%1,%2,%3};" \
        : "+f"((c)[0]), "+f"((c)[1]), "+f"((c)[2]), "+f"((c)[3]) \
        : "r"((a)[0]), "r"((a)[1]), "r"((a)[2]), "r"((a)[3]), \
          "r"((b)[0]), "r"((b)[1]))

__global__ __launch_bounds__(256, 2)
void k_approx(const float* __restrict__ x) {
    extern __shared__ unsigned char sm[];
    __nv_bfloat16* xs = (__nv_bfloat16*)sm;
    __nv_bfloat16* eb = (__nv_bfloat16*)(sm + SM_EB_OFF);
    __nv_bfloat16* scores = (__nv_bfloat16*)(sm + SM_SC_OFF);
    float* e2s = (float*)(sm + SM_E2_OFF);
    const unsigned xs_a = smem_u32(xs);
    const unsigned eb_a = smem_u32(eb);

    const int tid = threadIdx.x, w = tid >> 5, lane = tid & 31;
    const int R0 = blockIdx.x * 128;

    for (int i = tid; i < 1024; i += 256) e2s[i] = g_e2[i];

    // prefetch e chunk 0
    {
        const unsigned char* src = (const unsigned char*)g_ebf;
        unsigned char* dst = (unsigned char*)eb;
        for (int i = tid; i < 2048; i += 256) {
            int r = i >> 4, o = (i & 15) * 16;
            __pipeline_memcpy_async(dst + r * 272 + o, src + r * 256 + o, 16);
        }
        __pipeline_commit();
    }

    // x tile -> bf16 smem [row][k]
    {
        const float4* x4 = (const float4*)x;
        for (int i = tid; i < 4096; i += 256) {
            int r = i >> 5, kg = i & 31;
            float4 v = x4[(long)(R0 + r) * 32 + kg];
            __nv_bfloat162 p0 = __floats2bfloat162_rn(v.x, v.y);
            __nv_bfloat162 p1 = __floats2bfloat162_rn(v.z, v.w);
            *(uint2*)&xs[r * XES + kg * 4] =
                make_uint2(*(unsigned*)&p0, *(unsigned*)&p1);
        }
    }

    const int rg = w >> 1;                 // row group (32 rows)
    const int cg = w & 1;                  // code half (64 codes)
    const int rbase = rg * 32;

    float runmin = FLT_MAX;
    int cnt = 0;
    unsigned short* crow = g_cand + ((long)R0 + tid) * CAND_MAX;

    for (int ch = 0; ch < CHUNKS; ch++) {
        __pipeline_wait_prior(0);
        __syncthreads();                   // eb(ch) ready; prev scan done

        float acc[2][8][4];
#pragma unroll
        for (int mt = 0; mt < 2; mt++)
#pragma unroll
            for (int nt = 0; nt < 8; nt++)
#pragma unroll
                for (int q = 0; q < 4; q++) acc[mt][nt][q] = 0.0f;

#pragma unroll
        for (int ks = 0; ks < 8; ks++) {
            unsigned a[2][4];
#pragma unroll
            for (int mt = 0; mt < 2; mt++) {
                int row = rbase + mt * 16 + (lane & 7) + ((lane >> 3) & 1) * 8;
                int ko  = ks * 16 + (lane >> 4) * 8;
                unsigned ad = xs_a + (unsigned)(row * XES + ko) * 2;
                LDMX4(a[mt][0], a[mt][1], a[mt][2], a[mt][3], ad);
            }
            unsigned b[8][2];
#pragma unroll
            for (int p = 0; p < 4; p++) {
                int g = lane >> 3, ri = lane & 7;
                int code = cg * 64 + p * 16 + (g >> 1) * 8 + ri;
                int ko   = ks * 16 + (g & 1) * 8;
                unsigned ad = eb_a + (unsigned)(code * XES + ko) * 2;
                LDMX4(b[2 * p][0], b[2 * p][1], b[2 * p + 1][0], b[2 * p + 1][1], ad);
            }
#pragma unroll
            for (int mt = 0; mt < 2; mt++)
#pragma unroll
                for (int nt = 0; nt < 8; nt++)
                    MMA16816(acc[mt][nt], a[mt], b[nt]);
        }

        // scores (bf16) = e2 - 2*dot
#pragma unroll
        for (int mt = 0; mt < 2; mt++)
#pragma unroll
            for (int nt = 0; nt < 8; nt++) {
                int row = rbase + mt * 16 + (lane >> 2);
                int col = cg * 64 + nt * 8 + (lane & 3) * 2;
                float e2a = e2s[ch * CN + col], e2b = e2s[ch * CN + col + 1];
                __nv_bfloat162 p0 = __floats2bfloat162_rn(
                    fmaf(-2.0f, acc[mt][nt][0], e2a),
                    fmaf(-2.0f, acc[mt][nt][1], e2b));
                __nv_bfloat162 p1 = __floats2bfloat162_rn(
                    fmaf(-2.0f, acc[mt][nt][2], e2a),
                    fmaf(-2.0f, acc[mt][nt][3], e2b));
                *(unsigned*)&scores[row * SCS + col] = *(unsigned*)&p0;
                *(unsigned*)&scores[(row + 8) * SCS + col] = *(unsigned*)&p1;
            }
        __syncthreads();                   // eb free; scores ready

        // prefetch chunk ch+1 into eb (overlaps scan below)
        if (ch + 1 < CHUNKS) {
            const unsigned char* src =
                (const unsigned char*)g_ebf + (ch + 1) * CN * 256;
            unsigned char* dst = (unsigned char*)eb;
            for (int i = tid; i < 2048; i += 256) {
                int r = i >> 4, o = (i & 15) * 16;
                __pipeline_memcpy_async(dst + r * 272 + o, src + r * 256 + o, 16);
            }
        }
        __pipeline_commit();

        // per-row scan (thread tid < 128 owns row tid)
        if (tid < 128) {
            const __nv_bfloat16* sr = &scores[tid * SCS];
            float rm = runmin;
#pragma unroll 4
            for (int c = 0; c < CN; c++) {
                float s = __bfloat162float(sr[c]);
                if (s < rm + MARGIN) {
                    if (cnt < CAND_MAX) crow[cnt] = (unsigned short)(ch * CN + c);
                    cnt++;
                    if (s < rm) rm = s;
                }
            }
            runmin = rm;
        }
    }
    if (tid < 128) g_ccnt[R0 + tid] = cnt;   // >CAND_MAX => k_final full-scan
}

// ---------------------------------------------------------------------------
// Pass B1: exact rescore. Warp per row, lane per candidate.
// Bit-exact R7 chain: serial ascending-k fp32 FMA; s = fl(fl(e2+x2)-2*dot).
// ---------------------------------------------------------------------------
__global__ __launch_bounds__(256)
void k_rescore(const float* __restrict__ x, const float* __restrict__ emb) {
    const long row = (long)blockIdx.x * 8 + (threadIdx.x >> 5);
    const int lane = threadIdx.x & 31;
    const int cnt = g_ccnt[row];
    float s = FLT_MAX;
    if (cnt <= CAND_MAX && lane < cnt) {
        int code = g_cand[row * CAND_MAX + lane];
        const float4* xr = (const float4*)(x + row * 128);
        const float4* er = (const float4*)(emb + (long)code * 128);
        float acc = 0.0f;
#pragma unroll 8
        for (int i = 0; i < 32; i++) {
            float4 a = xr[i], b = er[i];
            acc = fmaf(a.x, b.x, acc);
            acc = fmaf(a.y, b.y, acc);
            acc = fmaf(a.z, b.z, acc);
            acc = fmaf(a.w, b.w, acc);
        }
        s = __fadd_rn(__fadd_rn(g_e2[code], g_x2[row]), __fmul_rn(-2.0f, acc));
    }
    g_cs[row * CAND_MAX + lane] = s;
}

// ---------------------------------------------------------------------------
// Pass B2: winner selection + epilogue. Warp per row, lane per float4.
// ---------------------------------------------------------------------------
__global__ __launch_bounds__(256)
void k_final(const float* __restrict__ x, const float* __restrict__ emb,
             float* __restrict__ out_q, float* __restrict__ out_codes,
             int write_aux) {
    __shared__ float sl[8];
    const int w = threadIdx.x >> 5, lane = threadIdx.x & 31;
    const long row = (long)blockIdx.x * 8 + w;
    const int cnt = g_ccnt[row];

    float best; int bcode;
    if (cnt <= CAND_MAX) {
        best = g_cs[row * CAND_MAX + lane];
        bcode = (lane < cnt) ? (int)g_cand[row * CAND_MAX + lane] : 0x7fffffff;
    } else {
        // rare overflow: exact scan of all codes, lane covers lane+32t
        const float4* xr = (const float4*)(x + row * 128);
        const float x2v = g_x2[row];
        best = FLT_MAX; bcode = 0x7fffffff;
        for (int t = 0; t < 32; t++) {
            int code = lane + t * 32;
            const float4* er = (const float4*)(emb + (long)code * 128);
            float acc = 0.0f;
#pragma unroll 8
            for (int i = 0; i < 32; i++) {
                float4 a = xr[i], b = er[i];
                acc = fmaf(a.x, b.x, acc);
                acc = fmaf(a.y, b.y, acc);
                acc = fmaf(a.z, b.z, acc);
                acc = fmaf(a.w, b.w, acc);
            }
            float s = __fadd_rn(__fadd_rn(g_e2[code], x2v), __fmul_rn(-2.0f, acc));
            if (s < best || (s == best && code < bcode)) { best = s; bcode = code; }
        }
    }
    // lexicographic (score, code) butterfly -> first-index argmin
#pragma unroll
    for (int o = 16; o > 0; o >>= 1) {
        float ob = __shfl_xor_sync(0xffffffffu, best, o);
        int   oc = __shfl_xor_sync(0xffffffffu, bcode, o);
        if (ob < best || (ob == best && oc < bcode)) { best = ob; bcode = oc; }
    }
    const int code = bcode;

    // coalesced epilogue: lane owns float4 dv=lane
    float4 xv = ((const float4*)x)[row * 32 + lane];
    float4 qv = ((const float4*)emb)[(long)code * 32 + lane];
    float4 o;
    o.x = __fadd_rn(xv.x, __fsub_rn(qv.x, xv.x));
    o.y = __fadd_rn(xv.y, __fsub_rn(qv.y, xv.y));
    o.z = __fadd_rn(xv.z, __fsub_rn(qv.z, xv.z));
    o.w = __fadd_rn(xv.w, __fsub_rn(qv.w, xv.w));
    ((float4*)out_q)[row * 32 + lane] = o;

    float dx = xv.x - qv.x, dy = xv.y - qv.y, dz = xv.z - qv.z, dw_ = xv.w - qv.w;
    float lsum = dx * dx + dy * dy + dz * dz + dw_ * dw_;

    float* dwp = &g_dw[code * 128 + lane * 4];
    atomicAdd(dwp + 0, xv.x);
    atomicAdd(dwp + 1, xv.y);
    atomicAdd(dwp + 2, xv.z);
    atomicAdd(dwp + 3, xv.w);

    if (lane == 0) {
        atomicAdd(&g_counts[code], 1.0f);
        if (write_aux) out_codes[row] = (float)code;
    }
#pragma unroll
    for (int o2 = 16; o2 > 0; o2 >>= 1)
        lsum += __shfl_xor_sync(0xffffffffu, lsum, o2);
    if (lane == 0) sl[w] = lsum;
    __syncthreads();
    if (threadIdx.x == 0) {
        float t = 0.0f;
#pragma unroll
        for (int i = 0; i < 8; i++) t += sl[i];
        atomicAdd(&g_loss, t);
    }
}

// ---------------------------------------------------------------------------
// EMA scalar part (validated R7)
// ---------------------------------------------------------------------------
__global__ void k_ema1(const float* __restrict__ ema_count,
                       float* __restrict__ out_count,
                       float* __restrict__ out_loss,
                       float* __restrict__ out_perp) {
    __shared__ float sred[1024];
    int m = threadIdx.x;
    float cnt = g_counts[m];
    float raw = DECAYF * ema_count[m] + (1.0f - DECAYF) * cnt;
    sred[m] = raw;
    __syncthreads();
    for (int s = 512; s > 0; s >>= 1) {
        if (m < s) sred[m] += sred[m + s];
        __syncthreads();
    }
    float n = sred[0];
    __syncthreads();
    float newc = (raw + EPSF) / (n + 1024.0f * EPSF) * n;
    out_count[m] = newc;

    float p = cnt * (1.0f / 131072.0f);
    sred[m] = -p * logf(p + 1e-10f);
    __syncthreads();
    for (int s = 512; s > 0; s >>= 1) {
        if (m < s) sred[m] += sred[m + s];
        __syncthreads();
    }
    if (m == 0) {
        *out_perp = expf(sred[0]);
        *out_loss = 0.25f * g_loss * (1.0f / 16777216.0f);
    }
}

// ---------------------------------------------------------------------------
// EMA vector part (validated R7)
// ---------------------------------------------------------------------------
__global__ void k_ema2(const float* __restrict__ ema_weight,
                       const float* __restrict__ newc,
                       float* __restrict__ out_w,
                       float* __restrict__ out_emb) {
    int i = blockIdx.x * 256 + threadIdx.x;
    float w = DECAYF * ema_weight[i] + (1.0f - DECAYF) * g_dw[i];
    out_w[i] = w;
    out_emb[i] = w / newc[i >> 7];
}

// ---------------------------------------------------------------------------
extern "C" void kernel_launch(void* const* d_in, const int* in_sizes, int n_in,
                              void* d_out, int out_size) {
    const float* x          = (const float*)d_in[0];
    const float* emb        = (const float*)d_in[1];
    const float* ema_count  = (const float*)d_in[2];
    const float* ema_weight = (const float*)d_in[3];
    float* out = (float*)d_out;

    const int full = (out_size >= (int)OUT_TOTAL) ? 1 : 0;

    cudaFuncSetAttribute(k_approx, cudaFuncAttributeMaxDynamicSharedMemorySize,
                         SMEMA_BYTES);

    k_prep<<<512, 256>>>(emb);
    k_x2<<<NROWS / 2, 128>>>(x);
    k_approx<<<NROWS / 128, 256, SMEMA_BYTES>>>(x);
    k_rescore<<<NROWS / 8, 256>>>(x, emb);
    k_final<<<NROWS / 8, 256>>>(x, emb, out + OFF_Q,
                                full ? (out + OFF_CODES) : (out + OFF_Q), full);
    if (full) {
        k_ema1<<<1, 1024>>>(ema_count, out + OFF_CNT, out + OFF_LOSS,
                            out + OFF_PERP);
        k_ema2<<<512, 256>>>(ema_weight, out + OFF_CNT, out + OFF_W,
                             out + OFF_EMB);
    }
}